// round 9
// baseline (speedup 1.0000x reference)
#include <cuda_runtime.h>
#include <cuda_fp16.h>

#define N_NODES 100000
#define E_EDGES 1600000
#define IN_C    32
#define HID     32
#define OUT_C   8
#define EDGE_D  16
#define GRAPH_D 16

// ---------------- device scratch ----------------
__device__ float g_hi [N_NODES * HID];
__device__ uint4 g_Prh[N_NODES * 2];        // fp16 P_r rows (32B), bias+hG folded
__device__ uint4 g_Pch[N_NODES * 2];        // fp16 P_c rows
__device__ uint4 g_mNh[N_NODES * 2];        // fp16 mN accumulator rows (32B)
__device__ float g_h2 [N_NODES * HID];
__device__ float g_t  [N_NODES];
__device__ float g_rcnt[N_NODES];
__device__ float g_ccnt[N_NODES];
__device__ float g_hG [GRAPH_D];
__device__ float g_S0 [HID];
__device__ float g_S1 [HID];

__device__ __forceinline__ void red_add_v4h2(void* addr, unsigned a, unsigned b,
                                             unsigned c, unsigned d) {
    asm volatile("red.global.add.noftz.v4.f16x2 [%0], {%1,%2,%3,%4};"
                 :: "l"(addr), "r"(a), "r"(b), "r"(c), "r"(d) : "memory");
}

// ---------------- graph embedding + zero S0/S1 ----------------
__global__ void k_hG(const float* __restrict__ ga, const float* __restrict__ Wg,
                     const float* __restrict__ bg) {
    int j = threadIdx.x;
    if (j < GRAPH_D) {
        float acc = bg[j];
        #pragma unroll
        for (int k = 0; k < GRAPH_D; k++) acc += ga[k] * Wg[k * GRAPH_D + j];
        g_hG[j] = acc;
    }
    if (j < HID) { g_S0[j] = 0.f; g_S1[j] = 0.f; }
}

// ---------------- stream-B: zero degrees, then degrees ----------------
__global__ void __launch_bounds__(256)
k_zeroDeg() {
    int n = blockIdx.x * blockDim.x + threadIdx.x;
    if (n < N_NODES) { g_rcnt[n] = 0.f; g_ccnt[n] = 0.f; g_t[n] = 0.f; }
}

__global__ void __launch_bounds__(256)
k_deg(const int* __restrict__ ei) {
    int e = blockIdx.x * blockDim.x + threadIdx.x;
    if (e >= E_EDGES) return;
    atomicAdd(&g_rcnt[ei[e]], 1.f);
    atomicAdd(&g_ccnt[ei[E_EDGES + e]], 1.f);
}

// ---------------- stream-B: t accumulation (after edge1, beside node2) ----------------
__global__ void __launch_bounds__(256)
k_edge2(const int* __restrict__ ei) {
    int e = blockIdx.x * blockDim.x + threadIdx.x;
    if (e >= E_EDGES) return;
    int row = ei[e];
    int col = ei[E_EDGES + e];
    float w = 1.f / fmaxf(g_ccnt[col], 1.f);
    atomicAdd(&g_t[row], w);
}

// ---------------- k_hi: h_i = x@Wn + b — 2 threads/node, lane owns 16 channels ----------------
__global__ void __launch_bounds__(256)
k_hi(const float* __restrict__ x,
     const float* __restrict__ Wn, const float* __restrict__ bn) {
    __shared__ float Wns[IN_C * HID];
    __shared__ float bns[HID];
    for (int t = threadIdx.x; t < IN_C * HID; t += blockDim.x) Wns[t] = Wn[t];
    if (threadIdx.x < HID) bns[threadIdx.x] = bn[threadIdx.x];
    __syncthreads();

    int t = blockIdx.x * blockDim.x + threadIdx.x;
    int n = t >> 1;
    if (n >= N_NODES) return;
    int h = t & 1;                       // lane owns channels [16h, 16h+16)

    // zero fp16 mN row half (16B per lane)
    g_mNh[n * 2 + h] = make_uint4(0u, 0u, 0u, 0u);

    float acc[16];
    #pragma unroll
    for (int j = 0; j < 16; j++) acc[j] = bns[h * 16 + j];

    const float4* xr = reinterpret_cast<const float4*>(x + (size_t)n * IN_C);
    #pragma unroll
    for (int k4 = 0; k4 < IN_C / 4; k4++) {
        float4 v = xr[k4];               // paired lanes load same address: 1 sector
        float vv[4] = {v.x, v.y, v.z, v.w};
        #pragma unroll
        for (int q = 0; q < 4; q++) {
            float xv = vv[q];
            int k = k4 * 4 + q;
            #pragma unroll
            for (int j = 0; j < 16; j++) acc[j] += xv * Wns[k * HID + h * 16 + j];
        }
    }
    float4* ho = reinterpret_cast<float4*>(g_hi + (size_t)n * HID + h * 16);
    #pragma unroll
    for (int j4 = 0; j4 < 4; j4++)
        ho[j4] = make_float4(acc[j4*4], acc[j4*4+1], acc[j4*4+2], acc[j4*4+3]);
}

// ---------------- k_P: Pr/Pc (fp16) — 2 threads/node, lane owns 8 channels ----------------
__global__ void __launch_bounds__(256)
k_P(const float* __restrict__ Wea, const float* __restrict__ bea) {
    __shared__ float Weas[64 * EDGE_D];
    __shared__ float base_s[EDGE_D];
    for (int t = threadIdx.x; t < 64 * EDGE_D; t += blockDim.x) Weas[t] = Wea[t];
    if (threadIdx.x < EDGE_D) {
        int j = threadIdx.x;
        float b = bea[j];
        #pragma unroll
        for (int k = 0; k < GRAPH_D; k++)
            b += g_hG[k] * Wea[(80 + k) * EDGE_D + j];
        base_s[j] = b;
    }
    __syncthreads();

    int t = blockIdx.x * blockDim.x + threadIdx.x;
    int n = t >> 1;
    if (n >= N_NODES) return;
    int h = t & 1;                       // lane owns P channels [8h, 8h+8)

    float pr[8], pc[8];
    #pragma unroll
    for (int j = 0; j < 8; j++) { pr[j] = base_s[h * 8 + j]; pc[j] = 0.f; }

    const float4* hr = reinterpret_cast<const float4*>(g_hi + (size_t)n * HID);
    #pragma unroll
    for (int k4 = 0; k4 < HID / 4; k4++) {
        float4 v = hr[k4];               // paired lanes same address
        float vv[4] = {v.x, v.y, v.z, v.w};
        #pragma unroll
        for (int q = 0; q < 4; q++) {
            float hv = vv[q];
            int k = k4 * 4 + q;
            #pragma unroll
            for (int j = 0; j < 8; j++) {
                pr[j] += hv * Weas[k * EDGE_D + h * 8 + j];
                pc[j] += hv * Weas[(32 + k) * EDGE_D + h * 8 + j];
            }
        }
    }
    union { __half2 h2[4]; uint4 u4; } pk, qk;
    #pragma unroll
    for (int j = 0; j < 4; j++) {
        pk.h2[j] = __floats2half2_rn(pr[2*j], pr[2*j+1]);
        qk.h2[j] = __floats2half2_rn(pc[2*j], pc[2*j+1]);
    }
    g_Prh[n * 2 + h] = pk.u4;
    g_Pch[n * 2 + h] = qk.u4;
}

// ---------------- edge pass 1 — 4 threads/edge, fp16 in + fp16 red out ----------------
__global__ void __launch_bounds__(256)
k_edge1(const int* __restrict__ ei,
        const float* __restrict__ edge_attr,
        const float* __restrict__ Wea) {
    __shared__ float Wc[EDGE_D * EDGE_D];
    __shared__ float eas[256 * 4];
    for (int t = threadIdx.x; t < EDGE_D * EDGE_D; t += blockDim.x)
        Wc[t] = Wea[64 * EDGE_D + t];
    __syncthreads();

    int t = blockIdx.x * blockDim.x + threadIdx.x;
    int e = t >> 2;
    int c = threadIdx.x & 3;

    int row = ei[e];
    int col = ei[E_EDGES + e];

    uint2 pru = reinterpret_cast<const uint2*>(g_Prh)[(size_t)row * 4 + c];
    uint2 pcu = reinterpret_cast<const uint2*>(g_Pch)[(size_t)col * 4 + c];
    float2 fr01 = __half22float2(*reinterpret_cast<__half2*>(&pru.x));
    float2 fr23 = __half22float2(*reinterpret_cast<__half2*>(&pru.y));
    float2 fc01 = __half22float2(*reinterpret_cast<__half2*>(&pcu.x));
    float2 fc23 = __half22float2(*reinterpret_cast<__half2*>(&pcu.y));

    float4 ea = *reinterpret_cast<const float4*>(edge_attr + (size_t)e * EDGE_D + c * 4);
    reinterpret_cast<float4*>(eas)[threadIdx.x] = ea;
    __syncwarp();
    const float4* eg = reinterpret_cast<const float4*>(eas + (threadIdx.x & ~3) * 4);

    float acc[4] = {fr01.x + fc01.x, fr01.y + fc01.y,
                    fr23.x + fc23.x, fr23.y + fc23.y};

    #pragma unroll
    for (int k4 = 0; k4 < 4; k4++) {
        float4 evv = eg[k4];
        float ev[4] = {evv.x, evv.y, evv.z, evv.w};
        #pragma unroll
        for (int kk = 0; kk < 4; kk++) {
            int k = k4 * 4 + kk;
            #pragma unroll
            for (int j = 0; j < 4; j++)
                acc[j] += ev[kk] * Wc[k * EDGE_D + c * 4 + j];
        }
    }
    __half2 ha = __floats2half2_rn(fmaxf(acc[0], 0.f), fmaxf(acc[1], 0.f));
    __half2 hb = __floats2half2_rn(fmaxf(acc[2], 0.f), fmaxf(acc[3], 0.f));
    unsigned a0 = *reinterpret_cast<unsigned*>(&ha);
    unsigned a1 = *reinterpret_cast<unsigned*>(&hb);
    unsigned b0 = __shfl_xor_sync(0xFFFFFFFFu, a0, 1, 4);
    unsigned b1 = __shfl_xor_sync(0xFFFFFFFFu, a1, 1, 4);
    if ((c & 1) == 0) {
        __half* base = reinterpret_cast<__half*>(g_mNh + (size_t)row * 2) + (c >> 1) * 8;
        red_add_v4h2(base, a0, a1, b0, b1);
    }
}

// ---------------- node aggregator -> h_i2 — 2 threads/node ----------------
__global__ void __launch_bounds__(256)
k_node2(const float* __restrict__ Wna, const float* __restrict__ bna) {
    __shared__ float Wnas[48 * HID];
    __shared__ float base_s[HID];
    for (int t = threadIdx.x; t < 48 * HID; t += blockDim.x) Wnas[t] = Wna[t];
    if (threadIdx.x < HID) {
        float b = bna[threadIdx.x];
        #pragma unroll
        for (int k = 0; k < GRAPH_D; k++)
            b += g_hG[k] * Wna[(48 + k) * HID + threadIdx.x];
        base_s[threadIdx.x] = b;
    }
    __syncthreads();

    int t = blockIdx.x * blockDim.x + threadIdx.x;
    int n = t >> 1;
    if (n >= N_NODES) return;
    int h = t & 1;                       // lane owns channels [16h, 16h+16)

    float acc[16];
    #pragma unroll
    for (int j = 0; j < 16; j++) acc[j] = base_s[h * 16 + j];

    const float4* hr = reinterpret_cast<const float4*>(g_hi + (size_t)n * HID);
    #pragma unroll
    for (int k4 = 0; k4 < HID / 4; k4++) {
        float4 v = hr[k4];
        float vv[4] = {v.x, v.y, v.z, v.w};
        #pragma unroll
        for (int q = 0; q < 4; q++) {
            float hv = vv[q];
            int k = k4 * 4 + q;
            #pragma unroll
            for (int j = 0; j < 16; j++) acc[j] += hv * Wnas[k * HID + h * 16 + j];
        }
    }
    float inv_c = 1.f / fmaxf(g_rcnt[n], 1.f);
    union { uint4 u4[2]; __half2 h2[8]; } mu;
    mu.u4[0] = g_mNh[n * 2 + 0];
    mu.u4[1] = g_mNh[n * 2 + 1];
    #pragma unroll
    for (int p = 0; p < 8; p++) {
        float2 mf = __half22float2(mu.h2[p]);
        float m0 = mf.x * inv_c;
        float m1 = mf.y * inv_c;
        int k0 = 32 + 2 * p;
        #pragma unroll
        for (int j = 0; j < 16; j++) {
            acc[j] += m0 * Wnas[k0 * HID + h * 16 + j];
            acc[j] += m1 * Wnas[(k0 + 1) * HID + h * 16 + j];
        }
    }
    float4* h2o = reinterpret_cast<float4*>(g_h2 + (size_t)n * HID + h * 16);
    #pragma unroll
    for (int j4 = 0; j4 < 4; j4++)
        h2o[j4] = make_float4(fmaxf(acc[j4*4], 0.f),   fmaxf(acc[j4*4+1], 0.f),
                              fmaxf(acc[j4*4+2], 0.f), fmaxf(acc[j4*4+3], 0.f));
}

// ---------------- reduce S0 = sum h_i2, S1 = sum t*h_i2 ----------------
__global__ void __launch_bounds__(256)
k_reduce() {
    int lane = threadIdx.x & 31;
    int warp = (blockIdx.x * blockDim.x + threadIdx.x) >> 5;
    int nwarps = (gridDim.x * blockDim.x) >> 5;

    float s0 = 0.f, s1 = 0.f;
    for (int n = warp; n < N_NODES; n += nwarps) {
        float h = g_h2[(size_t)n * HID + lane];
        float tv = g_t[n];
        s0 += h;
        s1 += tv * h;
    }
    atomicAdd(&g_S0[lane], s0);
    atomicAdd(&g_S1[lane], s1);
}

// ---------------- pooled linear + log_softmax ----------------
__global__ void k_final(const float* __restrict__ Wl, const float* __restrict__ bl,
                        const float* __restrict__ Wr, float* __restrict__ out) {
    __shared__ float p[OUT_C];
    int j = threadIdx.x;
    if (j < OUT_C) {
        float acc = 0.f;
        #pragma unroll
        for (int k = 0; k < HID; k++)
            acc += g_S1[k] * Wl[k * OUT_C + j] + g_S0[k] * Wr[k * OUT_C + j];
        p[j] = bl[j] + acc * (1.f / (float)N_NODES);
    }
    __syncthreads();
    if (j == 0) {
        float mx = -1e30f;
        #pragma unroll
        for (int i = 0; i < OUT_C; i++) mx = fmaxf(mx, p[i]);
        float se = 0.f;
        #pragma unroll
        for (int i = 0; i < OUT_C; i++) se += expf(p[i] - mx);
        float lse = mx + logf(se);
        #pragma unroll
        for (int i = 0; i < OUT_C; i++) out[i] = p[i] - lse;
    }
}

// ---------------- launch ----------------
extern "C" void kernel_launch(void* const* d_in, const int* in_sizes, int n_in,
                              void* d_out, int out_size) {
    const float* x          = (const float*)d_in[0];
    const float* edge_attr  = (const float*)d_in[1];
    const float* graph_attr = (const float*)d_in[2];
    const int*   edge_index = (const int*)  d_in[3];
    const float* W_node     = (const float*)d_in[5];
    const float* b_node     = (const float*)d_in[6];
    const float* W_graph    = (const float*)d_in[7];
    const float* b_graph    = (const float*)d_in[8];
    const float* W_edge_agg = (const float*)d_in[9];
    const float* b_edge_agg = (const float*)d_in[10];
    const float* W_node_agg = (const float*)d_in[11];
    const float* b_node_agg = (const float*)d_in[12];
    const float* W_sage_l   = (const float*)d_in[13];
    const float* b_sage_l   = (const float*)d_in[14];
    const float* W_sage_r   = (const float*)d_in[15];
    float* out = (float*)d_out;

    static cudaStream_t sB = nullptr;
    static cudaEvent_t evFork = nullptr, evDeg = nullptr, evE1 = nullptr, evT = nullptr;
    if (sB == nullptr) {
        cudaStreamCreateWithFlags(&sB, cudaStreamNonBlocking);
        cudaEventCreateWithFlags(&evFork, cudaEventDisableTiming);
        cudaEventCreateWithFlags(&evDeg, cudaEventDisableTiming);
        cudaEventCreateWithFlags(&evE1, cudaEventDisableTiming);
        cudaEventCreateWithFlags(&evT, cudaEventDisableTiming);
    }

    const int TB = 256;
    const int nodeBlocks  = (N_NODES + TB - 1) / TB;
    const int node2Blocks = (N_NODES * 2 + TB - 1) / TB;
    const int edge1Blocks = (E_EDGES * 4) / TB;
    const int edgeBlocks  = (E_EDGES + TB - 1) / TB;

    k_hG<<<1, 32>>>(graph_attr, W_graph, b_graph);

    // stream B: degrees — no edge1 dependency, free to overlap everything up to node2
    cudaEventRecord(evFork, 0);
    cudaStreamWaitEvent(sB, evFork, 0);
    k_zeroDeg<<<nodeBlocks, TB, 0, sB>>>();
    k_deg<<<edgeBlocks, TB, 0, sB>>>(edge_index);
    cudaEventRecord(evDeg, sB);

    // main stream
    k_hi<<<node2Blocks, TB>>>(x, W_node, b_node);
    k_P<<<node2Blocks, TB>>>(W_edge_agg, b_edge_agg);
    k_edge1<<<edge1Blocks, TB>>>(edge_index, edge_attr, W_edge_agg);
    cudaEventRecord(evE1, 0);

    // stream B: t accumulation beside node2 (needs ccnt + edge1 done for ordering of mN? no — only ccnt)
    cudaStreamWaitEvent(sB, evE1, 0);
    k_edge2<<<edgeBlocks, TB, 0, sB>>>(edge_index);
    cudaEventRecord(evT, sB);

    cudaStreamWaitEvent(0, evDeg, 0);   // node2 needs rcnt
    k_node2<<<node2Blocks, TB>>>(W_node_agg, b_node_agg);

    cudaStreamWaitEvent(0, evT, 0);     // reduce needs t
    k_reduce<<<128, TB>>>();
    k_final<<<1, 32>>>(W_sage_l, b_sage_l, W_sage_r, out);
}

// round 10
// speedup vs baseline: 1.0429x; 1.0429x over previous
#include <cuda_runtime.h>
#include <cuda_fp16.h>

#define N_NODES 100000
#define E_EDGES 1600000
#define IN_C    32
#define HID     32
#define OUT_C   8
#define EDGE_D  16
#define GRAPH_D 16

// ---------------- device scratch ----------------
__device__ uint4 g_Prh[N_NODES * 2];        // fp16 P_r rows (32B), all biases folded
__device__ uint4 g_Pch[N_NODES * 2];        // fp16 P_c rows
__device__ uint4 g_mNh[N_NODES * 2];        // fp16 mN accumulator rows (32B)
__device__ float g_h2 [N_NODES * HID];
__device__ float g_t  [N_NODES];
__device__ float g_rcnt[N_NODES];
__device__ float g_ccnt[N_NODES];
__device__ float g_S0 [HID];
__device__ float g_S1 [HID];
// folded weights (built per-launch by k_fold)
__device__ float g_Wpr [IN_C * EDGE_D];     // Wn @ Wea[0:32]
__device__ float g_Wpc [IN_C * EDGE_D];     // Wn @ Wea[32:64]
__device__ float g_Wx  [IN_C * HID];        // Wn @ Wna[0:32]
__device__ float g_bpr [EDGE_D];            // b_edge + hG@Wea[80:96] + b_node@Wea[0:32]
__device__ float g_bna [HID];               // b_na + hG@Wna[48:64] + b_node@Wna[0:32]

__device__ __forceinline__ void red_add_v4h2(void* addr, unsigned a, unsigned b,
                                             unsigned c, unsigned d) {
    asm volatile("red.global.add.noftz.v4.f16x2 [%0], {%1,%2,%3,%4};"
                 :: "l"(addr), "r"(a), "r"(b), "r"(c), "r"(d) : "memory");
}

// ---------------- k_fold: build folded weight matrices (tiny, one block) ----------------
__global__ void __launch_bounds__(1024)
k_fold(const float* __restrict__ ga, const float* __restrict__ Wg,
       const float* __restrict__ bg,
       const float* __restrict__ Wn, const float* __restrict__ bn,
       const float* __restrict__ Wea, const float* __restrict__ bea,
       const float* __restrict__ Wna, const float* __restrict__ bna) {
    __shared__ float hG[GRAPH_D];
    int tid = threadIdx.x;
    // graph embedding
    if (tid < GRAPH_D) {
        float acc = bg[tid];
        #pragma unroll
        for (int k = 0; k < GRAPH_D; k++) acc += ga[k] * Wg[k * GRAPH_D + tid];
        hG[tid] = acc;
    }
    if (tid < HID) { g_S0[tid] = 0.f; g_S1[tid] = 0.f; }
    __syncthreads();

    // Wpr/Wpc: 32x16 each  (tid = r*16+j over 512 threads each)
    if (tid < IN_C * EDGE_D) {
        int r = tid / EDGE_D, j = tid % EDGE_D;
        float apr = 0.f, apc = 0.f;
        #pragma unroll
        for (int k = 0; k < HID; k++) {
            float w = Wn[r * HID + k];
            apr += w * Wea[k * EDGE_D + j];
            apc += w * Wea[(32 + k) * EDGE_D + j];
        }
        g_Wpr[tid] = apr;
        g_Wpc[tid] = apc;
    }
    // Wx: 32x32
    if (tid < IN_C * HID) {
        int r = tid / HID, j = tid % HID;
        float a = 0.f;
        #pragma unroll
        for (int k = 0; k < HID; k++)
            a += Wn[r * HID + k] * Wna[k * HID + j];
        g_Wx[tid] = a;
    }
    // biases
    if (tid < EDGE_D) {
        float b = bea[tid];
        #pragma unroll
        for (int k = 0; k < GRAPH_D; k++) b += hG[k] * Wea[(80 + k) * EDGE_D + tid];
        #pragma unroll
        for (int k = 0; k < HID; k++)     b += bn[k] * Wea[k * EDGE_D + tid];
        g_bpr[tid] = b;
    }
    if (tid >= 32 && tid < 32 + HID) {
        int j = tid - 32;
        float b = bna[j];
        #pragma unroll
        for (int k = 0; k < GRAPH_D; k++) b += hG[k] * Wna[(48 + k) * HID + j];
        #pragma unroll
        for (int k = 0; k < HID; k++)     b += bn[k] * Wna[k * HID + j];
        g_bna[j] = b;
    }
}

// ---------------- stream-B: zero degrees, then degrees ----------------
__global__ void __launch_bounds__(256)
k_zeroDeg() {
    int n = blockIdx.x * blockDim.x + threadIdx.x;
    if (n < N_NODES) { g_rcnt[n] = 0.f; g_ccnt[n] = 0.f; g_t[n] = 0.f; }
}

__global__ void __launch_bounds__(256)
k_deg(const int* __restrict__ ei) {
    int e = blockIdx.x * blockDim.x + threadIdx.x;
    if (e >= E_EDGES) return;
    atomicAdd(&g_rcnt[ei[e]], 1.f);
    atomicAdd(&g_ccnt[ei[E_EDGES + e]], 1.f);
}

// ---------------- stream-B: t accumulation (after edge1, beside node2) ----------------
__global__ void __launch_bounds__(256)
k_edge2(const int* __restrict__ ei) {
    int e = blockIdx.x * blockDim.x + threadIdx.x;
    if (e >= E_EDGES) return;
    int row = ei[e];
    int col = ei[E_EDGES + e];
    float w = 1.f / fmaxf(g_ccnt[col], 1.f);
    atomicAdd(&g_t[row], w);
}

// ---------------- k_nodeP: x -> Pr/Pc (fp16) directly + zero mN ----------------
__global__ void __launch_bounds__(256)
k_nodeP(const float* __restrict__ x) {
    __shared__ float Wprs[IN_C * EDGE_D];
    __shared__ float Wpcs[IN_C * EDGE_D];
    __shared__ float bprs[EDGE_D];
    for (int t = threadIdx.x; t < IN_C * EDGE_D; t += blockDim.x) {
        Wprs[t] = g_Wpr[t];
        Wpcs[t] = g_Wpc[t];
    }
    if (threadIdx.x < EDGE_D) bprs[threadIdx.x] = g_bpr[threadIdx.x];
    __syncthreads();

    int n = blockIdx.x * blockDim.x + threadIdx.x;
    if (n >= N_NODES) return;

    uint4 z4 = make_uint4(0u, 0u, 0u, 0u);
    g_mNh[n * 2 + 0] = z4;
    g_mNh[n * 2 + 1] = z4;

    float pr[EDGE_D], pc[EDGE_D];
    #pragma unroll
    for (int j = 0; j < EDGE_D; j++) { pr[j] = bprs[j]; pc[j] = 0.f; }

    const float4* xr = reinterpret_cast<const float4*>(x + (size_t)n * IN_C);
    #pragma unroll
    for (int k4 = 0; k4 < IN_C / 4; k4++) {
        float4 v = xr[k4];
        float vv[4] = {v.x, v.y, v.z, v.w};
        #pragma unroll
        for (int q = 0; q < 4; q++) {
            float xv = vv[q];
            int k = k4 * 4 + q;
            #pragma unroll
            for (int j = 0; j < EDGE_D; j++) {
                pr[j] += xv * Wprs[k * EDGE_D + j];
                pc[j] += xv * Wpcs[k * EDGE_D + j];
            }
        }
    }
    union { __half2 h2[8]; uint4 u4[2]; } pk, qk;
    #pragma unroll
    for (int j = 0; j < 8; j++) {
        pk.h2[j] = __floats2half2_rn(pr[2*j], pr[2*j+1]);
        qk.h2[j] = __floats2half2_rn(pc[2*j], pc[2*j+1]);
    }
    g_Prh[n * 2 + 0] = pk.u4[0];
    g_Prh[n * 2 + 1] = pk.u4[1];
    g_Pch[n * 2 + 0] = qk.u4[0];
    g_Pch[n * 2 + 1] = qk.u4[1];
}

// ---------------- edge pass 1 — 4 threads/edge, fp16 in + fp16 red out ----------------
__global__ void __launch_bounds__(256)
k_edge1(const int* __restrict__ ei,
        const float* __restrict__ edge_attr,
        const float* __restrict__ Wea) {
    __shared__ float Wc[EDGE_D * EDGE_D];
    __shared__ float eas[256 * 4];
    for (int t = threadIdx.x; t < EDGE_D * EDGE_D; t += blockDim.x)
        Wc[t] = Wea[64 * EDGE_D + t];
    __syncthreads();

    int t = blockIdx.x * blockDim.x + threadIdx.x;
    int e = t >> 2;
    int c = threadIdx.x & 3;

    int row = ei[e];
    int col = ei[E_EDGES + e];

    uint2 pru = reinterpret_cast<const uint2*>(g_Prh)[(size_t)row * 4 + c];
    uint2 pcu = reinterpret_cast<const uint2*>(g_Pch)[(size_t)col * 4 + c];
    float2 fr01 = __half22float2(*reinterpret_cast<__half2*>(&pru.x));
    float2 fr23 = __half22float2(*reinterpret_cast<__half2*>(&pru.y));
    float2 fc01 = __half22float2(*reinterpret_cast<__half2*>(&pcu.x));
    float2 fc23 = __half22float2(*reinterpret_cast<__half2*>(&pcu.y));

    float4 ea = *reinterpret_cast<const float4*>(edge_attr + (size_t)e * EDGE_D + c * 4);
    reinterpret_cast<float4*>(eas)[threadIdx.x] = ea;
    __syncwarp();
    const float4* eg = reinterpret_cast<const float4*>(eas + (threadIdx.x & ~3) * 4);

    float acc[4] = {fr01.x + fc01.x, fr01.y + fc01.y,
                    fr23.x + fc23.x, fr23.y + fc23.y};

    #pragma unroll
    for (int k4 = 0; k4 < 4; k4++) {
        float4 evv = eg[k4];
        float ev[4] = {evv.x, evv.y, evv.z, evv.w};
        #pragma unroll
        for (int kk = 0; kk < 4; kk++) {
            int k = k4 * 4 + kk;
            #pragma unroll
            for (int j = 0; j < 4; j++)
                acc[j] += ev[kk] * Wc[k * EDGE_D + c * 4 + j];
        }
    }
    __half2 ha = __floats2half2_rn(fmaxf(acc[0], 0.f), fmaxf(acc[1], 0.f));
    __half2 hb = __floats2half2_rn(fmaxf(acc[2], 0.f), fmaxf(acc[3], 0.f));
    unsigned a0 = *reinterpret_cast<unsigned*>(&ha);
    unsigned a1 = *reinterpret_cast<unsigned*>(&hb);
    unsigned b0 = __shfl_xor_sync(0xFFFFFFFFu, a0, 1, 4);
    unsigned b1 = __shfl_xor_sync(0xFFFFFFFFu, a1, 1, 4);
    if ((c & 1) == 0) {
        __half* base = reinterpret_cast<__half*>(g_mNh + (size_t)row * 2) + (c >> 1) * 8;
        red_add_v4h2(base, a0, a1, b0, b1);
    }
}

// ---------------- node aggregator -> h_i2 (reads x via folded Wx) ----------------
__global__ void __launch_bounds__(256)
k_node2(const float* __restrict__ x, const float* __restrict__ Wna) {
    __shared__ float Wxs[IN_C * HID];
    __shared__ float Wms[EDGE_D * HID];     // Wna rows 32..47 (mN part)
    __shared__ float base_s[HID];
    for (int t = threadIdx.x; t < IN_C * HID; t += blockDim.x) Wxs[t] = g_Wx[t];
    for (int t = threadIdx.x; t < EDGE_D * HID; t += blockDim.x)
        Wms[t] = Wna[32 * HID + t];
    if (threadIdx.x < HID) base_s[threadIdx.x] = g_bna[threadIdx.x];
    __syncthreads();

    int n = blockIdx.x * blockDim.x + threadIdx.x;
    if (n >= N_NODES) return;

    float acc[HID];
    #pragma unroll
    for (int j = 0; j < HID; j++) acc[j] = base_s[j];

    const float4* xr = reinterpret_cast<const float4*>(x + (size_t)n * IN_C);
    #pragma unroll
    for (int k4 = 0; k4 < IN_C / 4; k4++) {
        float4 v = xr[k4];
        float vv[4] = {v.x, v.y, v.z, v.w};
        #pragma unroll
        for (int q = 0; q < 4; q++) {
            float xv = vv[q];
            int k = k4 * 4 + q;
            #pragma unroll
            for (int j = 0; j < HID; j++) acc[j] += xv * Wxs[k * HID + j];
        }
    }
    float inv_c = 1.f / fmaxf(g_rcnt[n], 1.f);
    union { uint4 u4[2]; __half2 h2[8]; } mu;
    mu.u4[0] = g_mNh[n * 2 + 0];
    mu.u4[1] = g_mNh[n * 2 + 1];
    #pragma unroll
    for (int p = 0; p < 8; p++) {
        float2 mf = __half22float2(mu.h2[p]);
        float m0 = mf.x * inv_c;
        float m1 = mf.y * inv_c;
        int k0 = 2 * p;
        #pragma unroll
        for (int j = 0; j < HID; j++) {
            acc[j] += m0 * Wms[k0 * HID + j];
            acc[j] += m1 * Wms[(k0 + 1) * HID + j];
        }
    }
    float4* h2o = reinterpret_cast<float4*>(g_h2 + (size_t)n * HID);
    #pragma unroll
    for (int j4 = 0; j4 < HID / 4; j4++)
        h2o[j4] = make_float4(fmaxf(acc[j4*4], 0.f),   fmaxf(acc[j4*4+1], 0.f),
                              fmaxf(acc[j4*4+2], 0.f), fmaxf(acc[j4*4+3], 0.f));
}

// ---------------- reduce S0 = sum h_i2, S1 = sum t*h_i2 ----------------
__global__ void __launch_bounds__(256)
k_reduce() {
    int lane = threadIdx.x & 31;
    int warp = (blockIdx.x * blockDim.x + threadIdx.x) >> 5;
    int nwarps = (gridDim.x * blockDim.x) >> 5;

    float s0 = 0.f, s1 = 0.f;
    for (int n = warp; n < N_NODES; n += nwarps) {
        float h = g_h2[(size_t)n * HID + lane];
        float tv = g_t[n];
        s0 += h;
        s1 += tv * h;
    }
    atomicAdd(&g_S0[lane], s0);
    atomicAdd(&g_S1[lane], s1);
}

// ---------------- pooled linear + log_softmax ----------------
__global__ void k_final(const float* __restrict__ Wl, const float* __restrict__ bl,
                        const float* __restrict__ Wr, float* __restrict__ out) {
    __shared__ float p[OUT_C];
    int j = threadIdx.x;
    if (j < OUT_C) {
        float acc = 0.f;
        #pragma unroll
        for (int k = 0; k < HID; k++)
            acc += g_S1[k] * Wl[k * OUT_C + j] + g_S0[k] * Wr[k * OUT_C + j];
        p[j] = bl[j] + acc * (1.f / (float)N_NODES);
    }
    __syncthreads();
    if (j == 0) {
        float mx = -1e30f;
        #pragma unroll
        for (int i = 0; i < OUT_C; i++) mx = fmaxf(mx, p[i]);
        float se = 0.f;
        #pragma unroll
        for (int i = 0; i < OUT_C; i++) se += expf(p[i] - mx);
        float lse = mx + logf(se);
        #pragma unroll
        for (int i = 0; i < OUT_C; i++) out[i] = p[i] - lse;
    }
}

// ---------------- launch ----------------
extern "C" void kernel_launch(void* const* d_in, const int* in_sizes, int n_in,
                              void* d_out, int out_size) {
    const float* x          = (const float*)d_in[0];
    const float* edge_attr  = (const float*)d_in[1];
    const float* graph_attr = (const float*)d_in[2];
    const int*   edge_index = (const int*)  d_in[3];
    const float* W_node     = (const float*)d_in[5];
    const float* b_node     = (const float*)d_in[6];
    const float* W_graph    = (const float*)d_in[7];
    const float* b_graph    = (const float*)d_in[8];
    const float* W_edge_agg = (const float*)d_in[9];
    const float* b_edge_agg = (const float*)d_in[10];
    const float* W_node_agg = (const float*)d_in[11];
    const float* b_node_agg = (const float*)d_in[12];
    const float* W_sage_l   = (const float*)d_in[13];
    const float* b_sage_l   = (const float*)d_in[14];
    const float* W_sage_r   = (const float*)d_in[15];
    float* out = (float*)d_out;

    static cudaStream_t sB = nullptr;
    static cudaEvent_t evFork = nullptr, evDeg = nullptr, evE1 = nullptr, evT = nullptr;
    if (sB == nullptr) {
        cudaStreamCreateWithFlags(&sB, cudaStreamNonBlocking);
        cudaEventCreateWithFlags(&evFork, cudaEventDisableTiming);
        cudaEventCreateWithFlags(&evDeg, cudaEventDisableTiming);
        cudaEventCreateWithFlags(&evE1, cudaEventDisableTiming);
        cudaEventCreateWithFlags(&evT, cudaEventDisableTiming);
    }

    const int TB = 256;
    const int nodeBlocks  = (N_NODES + TB - 1) / TB;
    const int edge1Blocks = (E_EDGES * 4) / TB;
    const int edgeBlocks  = (E_EDGES + TB - 1) / TB;

    k_fold<<<1, 1024>>>(graph_attr, W_graph, b_graph, W_node, b_node,
                        W_edge_agg, b_edge_agg, W_node_agg, b_node_agg);

    // stream B: degrees, overlapped ONLY with compute-bound k_nodeP (R8 schedule)
    cudaEventRecord(evFork, 0);
    cudaStreamWaitEvent(sB, evFork, 0);
    k_zeroDeg<<<nodeBlocks, TB, 0, sB>>>();
    k_deg<<<edgeBlocks, TB, 0, sB>>>(edge_index);
    cudaEventRecord(evDeg, sB);

    // main stream
    k_nodeP<<<nodeBlocks, TB>>>(x);
    cudaStreamWaitEvent(0, evDeg, 0);   // keep deg traffic out of edge1's window
    k_edge1<<<edge1Blocks, TB>>>(edge_index, edge_attr, W_edge_agg);
    cudaEventRecord(evE1, 0);

    // stream B: t accumulation beside node2
    cudaStreamWaitEvent(sB, evE1, 0);
    k_edge2<<<edgeBlocks, TB, 0, sB>>>(edge_index);
    cudaEventRecord(evT, sB);

    k_node2<<<nodeBlocks, TB>>>(x, W_node_agg);

    cudaStreamWaitEvent(0, evT, 0);
    k_reduce<<<128, TB>>>();
    k_final<<<1, 32>>>(W_sage_l, b_sage_l, W_sage_r, out);
}